// round 6
// baseline (speedup 1.0000x reference)
#include <cuda_runtime.h>
#include <cstdint>

#define E_NUM   500000
#define H_DIM   256
#define PAIRS   (E_NUM / 2)      // 250000
#define BN_EPS  1e-5f
#define GRID    296              // 148 SMs x 2 co-resident blocks
#define PER1    848              // pairs/block for stats, blocks 1..295
#define PER2    845              // pairs/block for phase 2

typedef unsigned long long u64;

// -------- device scratch (static, no allocation) --------
__device__ float g_sum[H_DIM];                     // zero-init
__device__ float g_sumsq[H_DIM];
__device__ __align__(16) u64 g_nc2[PAIRS * 8];     // packed nc pairs, 16 MB
__device__ float g_Craw[H_DIM * 8];                // W2@Wv@Wo@Wp
__device__ float g_biaspart[8];                    // b2@P2 + bv@P1 + bo@Wp + bp
__device__ unsigned g_arrive = 0;
__device__ volatile unsigned g_release = 0;
__device__ unsigned g_finish = 0;

// -------- f32x2 helpers --------
__device__ __forceinline__ u64 pack2(float lo, float hi) {
    u64 r;
    asm("mov.b64 %0, {%1, %2};" : "=l"(r)
        : "r"(__float_as_uint(lo)), "r"(__float_as_uint(hi)));
    return r;
}
__device__ __forceinline__ void unpack2(u64 v, float &lo, float &hi) {
    unsigned int a, b;
    asm("mov.b64 {%0, %1}, %2;" : "=r"(a), "=r"(b) : "l"(v));
    lo = __uint_as_float(a); hi = __uint_as_float(b);
}
__device__ __forceinline__ u64 fma2(u64 a, u64 b, u64 c) {
    u64 d;
    asm("fma.rn.f32x2 %0, %1, %2, %3;" : "=l"(d) : "l"(a), "l"(b), "l"(c));
    return d;
}
__device__ __forceinline__ u64 mul2(u64 a, u64 b) {
    u64 d;
    asm("mul.rn.f32x2 %0, %1, %2;" : "=l"(d) : "l"(a), "l"(b));
    return d;
}
__device__ __forceinline__ u64 add2(u64 a, u64 b) {
    u64 d;
    asm("add.rn.f32x2 %0, %1, %2;" : "=l"(d) : "l"(a), "l"(b));
    return d;
}
__device__ __forceinline__ u64 relu2(u64 h) {
    float lo, hi; unpack2(h, lo, hi);
    return pack2(fmaxf(lo, 0.f), fmaxf(hi, 0.f));
}
__device__ __forceinline__ float wred(float v) {
    v += __shfl_down_sync(0xffffffffu, v, 16);
    v += __shfl_down_sync(0xffffffffu, v, 8);
    v += __shfl_down_sync(0xffffffffu, v, 4);
    v += __shfl_down_sync(0xffffffffu, v, 2);
    v += __shfl_down_sync(0xffffffffu, v, 1);
    return v;
}

__global__ void __launch_bounds__(256, 2)
fused(const float* __restrict__ ea, const float* __restrict__ nf,
      const int*   __restrict__ eidx,
      const float* __restrict__ W1, const float* __restrict__ b1,
      const float* __restrict__ gamma, const float* __restrict__ beta,
      const float* __restrict__ W2, const float* __restrict__ b2,
      const float* __restrict__ Wv, const float* __restrict__ bv,
      const float* __restrict__ Wo, const float* __restrict__ bo,
      const float* __restrict__ Wp, const float* __restrict__ bp,
      float* __restrict__ out)
{
    // union: phase1 ncs (u64[2048]) / block0 chain bufs (2x2304 floats) / phase2 ms
    __shared__ __align__(16) unsigned char s_buf[18432];
    __shared__ __align__(16) u64 w1s[H_DIM * 8];   // W1^T duplicated
    __shared__ u64 b1s[H_DIM];
    __shared__ u64 dh_s[8];
    __shared__ float a_s[H_DIM], c_s[H_DIM];

    const int t = threadIdx.x;
    const int b = blockIdx.x;
    const int lane = t & 31, warp = t >> 5;

    // duplicated W1^T / b1 tables
    #pragma unroll
    for (int d = 0; d < 8; d++) {
        float v = W1[d * H_DIM + t];
        w1s[t * 8 + d] = pack2(v, v);
    }
    { float bb = b1[t]; b1s[t] = pack2(bb, bb); }

    if (b == 0) {
        // ============ weight chain (overlaps the stats pass) ============
        float* bufA = (float*)s_buf;      // 256 rows x 9 floats (padded)
        float* bufB = bufA + 2304;
        for (int i = t; i < H_DIM * 8; i += 256)
            bufA[(i >> 3) * 9 + (i & 7)] = Wp[i];
        __syncthreads();
        float biask = 0.f;
        for (int j = lane; j < H_DIM; j += 32) biask += bo[j] * bufA[j * 9 + warp];
        // P1 = Wo @ Wp
        for (int jj = warp; jj < H_DIM; jj += 8) {
            float a0=0,a1=0,a2=0,a3=0,a4=0,a5=0,a6=0,a7=0;
            #pragma unroll
            for (int qb = 0; qb < 8; qb++) {
                int q = qb * 32 + lane;
                float av = Wo[jj * H_DIM + q];
                const float* ir = bufA + q * 9;
                a0 += av*ir[0]; a1 += av*ir[1]; a2 += av*ir[2]; a3 += av*ir[3];
                a4 += av*ir[4]; a5 += av*ir[5]; a6 += av*ir[6]; a7 += av*ir[7];
            }
            a0=wred(a0); a1=wred(a1); a2=wred(a2); a3=wred(a3);
            a4=wred(a4); a5=wred(a5); a6=wred(a6); a7=wred(a7);
            if (lane == 0) {
                float* orow = bufB + jj * 9;
                orow[0]=a0; orow[1]=a1; orow[2]=a2; orow[3]=a3;
                orow[4]=a4; orow[5]=a5; orow[6]=a6; orow[7]=a7;
            }
        }
        __syncthreads();
        for (int j = lane; j < H_DIM; j += 32) biask += bv[j] * bufB[j * 9 + warp];
        // P2 = Wv @ P1
        for (int jj = warp; jj < H_DIM; jj += 8) {
            float a0=0,a1=0,a2=0,a3=0,a4=0,a5=0,a6=0,a7=0;
            #pragma unroll
            for (int qb = 0; qb < 8; qb++) {
                int q = qb * 32 + lane;
                float av = Wv[jj * H_DIM + q];
                const float* ir = bufB + q * 9;
                a0 += av*ir[0]; a1 += av*ir[1]; a2 += av*ir[2]; a3 += av*ir[3];
                a4 += av*ir[4]; a5 += av*ir[5]; a6 += av*ir[6]; a7 += av*ir[7];
            }
            a0=wred(a0); a1=wred(a1); a2=wred(a2); a3=wred(a3);
            a4=wred(a4); a5=wred(a5); a6=wred(a6); a7=wred(a7);
            if (lane == 0) {
                float* orow = bufA + jj * 9;
                orow[0]=a0; orow[1]=a1; orow[2]=a2; orow[3]=a3;
                orow[4]=a4; orow[5]=a5; orow[6]=a6; orow[7]=a7;
            }
        }
        __syncthreads();
        for (int j = lane; j < H_DIM; j += 32) biask += b2[j] * bufA[j * 9 + warp];
        // Craw = W2 @ P2 -> global
        for (int jj = warp; jj < H_DIM; jj += 8) {
            float a0=0,a1=0,a2=0,a3=0,a4=0,a5=0,a6=0,a7=0;
            #pragma unroll
            for (int qb = 0; qb < 8; qb++) {
                int q = qb * 32 + lane;
                float av = W2[jj * H_DIM + q];
                const float* ir = bufA + q * 9;
                a0 += av*ir[0]; a1 += av*ir[1]; a2 += av*ir[2]; a3 += av*ir[3];
                a4 += av*ir[4]; a5 += av*ir[5]; a6 += av*ir[6]; a7 += av*ir[7];
            }
            a0=wred(a0); a1=wred(a1); a2=wred(a2); a3=wred(a3);
            a4=wred(a4); a5=wred(a5); a6=wred(a6); a7=wred(a7);
            if (lane == 0) {
                float* orow = g_Craw + jj * 8;
                orow[0]=a0; orow[1]=a1; orow[2]=a2; orow[3]=a3;
                orow[4]=a4; orow[5]=a5; orow[6]=a6; orow[7]=a7;
            }
        }
        biask = wred(biask);
        if (lane == 0) g_biaspart[warp] = biask + bp[warp];
    } else {
        // ============ phase 1: gather + cache nc + relu stats ============
        int s1 = (b - 1) * PER1;
        int e1 = s1 + PER1; if (e1 > PAIRS) e1 = PAIRS;
        u64* ncs = (u64*)s_buf;
        const float4* nf4 = (const float4*)nf;

        const ulonglong2* wd = (const ulonglong2*)&w1s[t * 8];
        ulonglong2 w01 = wd[0], w23 = wd[1], w45 = wd[2], w67 = wd[3];
        u64 bdup = b1s[t];
        u64 sum2 = 0ull, sq2 = 0ull;

        for (int base = s1; base < e1; base += 256) {
            int cnt = e1 - base; if (cnt > 256) cnt = 256;
            __syncthreads();
            if (t < cnt) {
                int p  = base + t;
                int e0 = 2 * p;
                int sA = eidx[e0],         sB = eidx[e0 + 1];
                int dA = eidx[E_NUM + e0], dB = eidx[E_NUM + e0 + 1];
                float4 sa0 = nf4[2*sA], sa1 = nf4[2*sA+1];
                float4 da0 = nf4[2*dA], da1 = nf4[2*dA+1];
                float4 sb0 = nf4[2*sB], sb1 = nf4[2*sB+1];
                float4 db0 = nf4[2*dB], db1 = nf4[2*dB+1];
                u64 ncp[8];
                ncp[0] = pack2(0.5f*(sa0.x+da0.x), 0.5f*(sb0.x+db0.x));
                ncp[1] = pack2(0.5f*(sa0.y+da0.y), 0.5f*(sb0.y+db0.y));
                ncp[2] = pack2(0.5f*(sa0.z+da0.z), 0.5f*(sb0.z+db0.z));
                ncp[3] = pack2(0.5f*(sa0.w+da0.w), 0.5f*(sb0.w+db0.w));
                ncp[4] = pack2(0.5f*(sa1.x+da1.x), 0.5f*(sb1.x+db1.x));
                ncp[5] = pack2(0.5f*(sa1.y+da1.y), 0.5f*(sb1.y+db1.y));
                ncp[6] = pack2(0.5f*(sa1.z+da1.z), 0.5f*(sb1.z+db1.z));
                ncp[7] = pack2(0.5f*(sa1.w+da1.w), 0.5f*(sb1.w+db1.w));
                #pragma unroll
                for (int d = 0; d < 8; d++) ncs[t * 8 + d] = ncp[d];
                ulonglong2* dst = (ulonglong2*)&g_nc2[(size_t)p * 8];
                dst[0] = make_ulonglong2(ncp[0], ncp[1]);
                dst[1] = make_ulonglong2(ncp[2], ncp[3]);
                dst[2] = make_ulonglong2(ncp[4], ncp[5]);
                dst[3] = make_ulonglong2(ncp[6], ncp[7]);
            }
            __syncthreads();
            // rotated/prefetched stats loop with split chains
            const ulonglong2* cs = (const ulonglong2*)ncs;
            ulonglong2 c01 = cs[0], c23 = cs[1], c45 = cs[2], c67 = cs[3];
            for (int e2 = 0; e2 < cnt; e2++) {
                int en = e2 + 1; if (en >= cnt) en = 0;
                ulonglong2 N01 = cs[en*4+0], N23 = cs[en*4+1];
                ulonglong2 N45 = cs[en*4+2], N67 = cs[en*4+3];
                u64 h1 = fma2(c01.x, w01.x, bdup);
                h1 = fma2(c01.y, w01.y, h1);
                h1 = fma2(c23.x, w23.x, h1);
                h1 = fma2(c23.y, w23.y, h1);
                u64 h2 = mul2(c45.x, w45.x);
                h2 = fma2(c45.y, w45.y, h2);
                h2 = fma2(c67.x, w67.x, h2);
                h2 = fma2(c67.y, w67.y, h2);
                u64 h = relu2(add2(h1, h2));
                sum2 = add2(sum2, h);
                sq2  = fma2(h, h, sq2);
                c01 = N01; c23 = N23; c45 = N45; c67 = N67;
            }
        }
        float slo, shi, qlo, qhi;
        unpack2(sum2, slo, shi);
        unpack2(sq2, qlo, qhi);
        atomicAdd(&g_sum[t],   slo + shi);
        atomicAdd(&g_sumsq[t], qlo + qhi);
    }

    // ============ grid barrier ============
    __syncthreads();
    if (t == 0) {
        __threadfence();
        if (atomicAdd(&g_arrive, 1) == GRID - 1) {
            g_release = 1;
        } else {
            while (g_release == 0) { }
        }
        __threadfence();
    }
    __syncthreads();

    // ============ finalize BN, dh, ms (per block) ============
    {
        const float invE = 1.f / (float)E_NUM;
        float mu  = g_sum[t] * invE;
        float var = g_sumsq[t] * invE - mu * mu;
        float aj  = gamma[t] * rsqrtf(var + BN_EPS);
        a_s[t] = aj;
        c_s[t] = beta[t] - mu * aj;
    }
    __syncthreads();
    {
        float acc = 0.f;
        for (int j = lane; j < H_DIM; j += 32) acc += c_s[j] * g_Craw[j * 8 + warp];
        acc = wred(acc);
        if (lane == 0) {
            float d = 0.5f * (acc + g_biaspart[warp]);
            dh_s[warp] = pack2(d, d);
        }
    }
    u64* ms = (u64*)s_buf;
    __syncthreads();
    for (int i = t; i < H_DIM * 8; i += 256) {
        float m = 0.5f * a_s[i >> 3] * g_Craw[i];
        ms[i] = pack2(m, m);
    }
    __syncthreads();

    // ============ phase 2: 2 pairs/thread, prefetch rotation, split chains ==
    int s2 = b * PER2;
    int e2p = s2 + PER2; if (e2p > PAIRS) e2p = PAIRS;
    const float4* ea4 = (const float4*)ea;
    float4* out4 = (float4*)out;
    const ulonglong2* wb = (const ulonglong2*)w1s;
    const ulonglong2* mb = (const ulonglong2*)ms;

    for (int base = s2; base < e2p; base += 512) {
        int pA = base + t;
        int pB = base + 256 + t;
        bool vA = pA < e2p, vB = pB < e2p;

        ulonglong2 nA0, nA1, nA2, nA3, nB0, nB1, nB2, nB3;
        if (vA) {
            const ulonglong2* g = (const ulonglong2*)&g_nc2[(size_t)pA * 8];
            nA0 = g[0]; nA1 = g[1]; nA2 = g[2]; nA3 = g[3];
        } else {
            nA0 = nA1 = nA2 = nA3 = make_ulonglong2(0ull, 0ull);
        }
        if (vB) {
            const ulonglong2* g = (const ulonglong2*)&g_nc2[(size_t)pB * 8];
            nB0 = g[0]; nB1 = g[1]; nB2 = g[2]; nB3 = g[3];
        } else {
            nB0 = nB1 = nB2 = nB3 = make_ulonglong2(0ull, 0ull);
        }

        u64 aA0 = dh_s[0], aA1 = dh_s[1], aA2 = dh_s[2], aA3 = dh_s[3];
        u64 aA4 = dh_s[4], aA5 = dh_s[5], aA6 = dh_s[6], aA7 = dh_s[7];
        u64 aB0 = aA0, aB1 = aA1, aB2 = aA2, aB3 = aA3;
        u64 aB4 = aA4, aB5 = aA5, aB6 = aA6, aB7 = aA7;

        // preload j=0 weights
        ulonglong2 w01 = wb[0], w23 = wb[1], w45 = wb[2], w67 = wb[3];
        u64 bb = b1s[0];

        #pragma unroll 2
        for (int j = 0; j < H_DIM; j++) {
            // prefetch next-j W1 row + bias (consumed next iteration)
            int jn = (j + 1) & (H_DIM - 1);
            ulonglong2 W01 = wb[4*jn+0], W23 = wb[4*jn+1];
            ulonglong2 W45 = wb[4*jn+2], W67 = wb[4*jn+3];
            u64 BB = b1s[jn];
            // m row for current j (consumed ~30cyc later, after h)
            ulonglong2 m01 = mb[4*j+0], m23 = mb[4*j+1];
            ulonglong2 m45 = mb[4*j+2], m67 = mb[4*j+3];

            u64 hA1 = fma2(nA0.x, w01.x, bb);
            hA1 = fma2(nA0.y, w01.y, hA1);
            hA1 = fma2(nA1.x, w23.x, hA1);
            hA1 = fma2(nA1.y, w23.y, hA1);
            u64 hA2 = mul2(nA2.x, w45.x);
            hA2 = fma2(nA2.y, w45.y, hA2);
            hA2 = fma2(nA3.x, w67.x, hA2);
            hA2 = fma2(nA3.y, w67.y, hA2);
            u64 hA = relu2(add2(hA1, hA2));

            u64 hB1 = fma2(nB0.x, w01.x, bb);
            hB1 = fma2(nB0.y, w01.y, hB1);
            hB1 = fma2(nB1.x, w23.x, hB1);
            hB1 = fma2(nB1.y, w23.y, hB1);
            u64 hB2 = mul2(nB2.x, w45.x);
            hB2 = fma2(nB2.y, w45.y, hB2);
            hB2 = fma2(nB3.x, w67.x, hB2);
            hB2 = fma2(nB3.y, w67.y, hB2);
            u64 hB = relu2(add2(hB1, hB2));

            aA0 = fma2(hA, m01.x, aA0); aA1 = fma2(hA, m01.y, aA1);
            aA2 = fma2(hA, m23.x, aA2); aA3 = fma2(hA, m23.y, aA3);
            aA4 = fma2(hA, m45.x, aA4); aA5 = fma2(hA, m45.y, aA5);
            aA6 = fma2(hA, m67.x, aA6); aA7 = fma2(hA, m67.y, aA7);
            aB0 = fma2(hB, m01.x, aB0); aB1 = fma2(hB, m01.y, aB1);
            aB2 = fma2(hB, m23.x, aB2); aB3 = fma2(hB, m23.y, aB3);
            aB4 = fma2(hB, m45.x, aB4); aB5 = fma2(hB, m45.y, aB5);
            aB6 = fma2(hB, m67.x, aB6); aB7 = fma2(hB, m67.y, aB7);

            // rotate
            w01 = W01; w23 = W23; w45 = W45; w67 = W67; bb = BB;
        }

        if (vA) {
            float4 e0 = ea4[4*pA+0], e1 = ea4[4*pA+1], e2 = ea4[4*pA+2], e3 = ea4[4*pA+3];
            float lo, hi; float4 o0, o1, o2, o3;
            unpack2(aA0, lo, hi); o0.x = e0.x + lo; o2.x = e2.x + hi;
            unpack2(aA1, lo, hi); o0.y = e0.y + lo; o2.y = e2.y + hi;
            unpack2(aA2, lo, hi); o0.z = e0.z + lo; o2.z = e2.z + hi;
            unpack2(aA3, lo, hi); o0.w = e0.w + lo; o2.w = e2.w + hi;
            unpack2(aA4, lo, hi); o1.x = e1.x + lo; o3.x = e3.x + hi;
            unpack2(aA5, lo, hi); o1.y = e1.y + lo; o3.y = e3.y + hi;
            unpack2(aA6, lo, hi); o1.z = e1.z + lo; o3.z = e3.z + hi;
            unpack2(aA7, lo, hi); o1.w = e1.w + lo; o3.w = e3.w + hi;
            out4[4*pA+0] = o0; out4[4*pA+1] = o1; out4[4*pA+2] = o2; out4[4*pA+3] = o3;
        }
        if (vB) {
            float4 e0 = ea4[4*pB+0], e1 = ea4[4*pB+1], e2 = ea4[4*pB+2], e3 = ea4[4*pB+3];
            float lo, hi; float4 o0, o1, o2, o3;
            unpack2(aB0, lo, hi); o0.x = e0.x + lo; o2.x = e2.x + hi;
            unpack2(aB1, lo, hi); o0.y = e0.y + lo; o2.y = e2.y + hi;
            unpack2(aB2, lo, hi); o0.z = e0.z + lo; o2.z = e2.z + hi;
            unpack2(aB3, lo, hi); o0.w = e0.w + lo; o2.w = e2.w + hi;
            unpack2(aB4, lo, hi); o1.x = e1.x + lo; o3.x = e3.x + hi;
            unpack2(aB5, lo, hi); o1.y = e1.y + lo; o3.y = e3.y + hi;
            unpack2(aB6, lo, hi); o1.z = e1.z + lo; o3.z = e3.z + hi;
            unpack2(aB7, lo, hi); o1.w = e1.w + lo; o3.w = e3.w + hi;
            out4[4*pB+0] = o0; out4[4*pB+1] = o1; out4[4*pB+2] = o2; out4[4*pB+3] = o3;
        }
    }

    // ============ reset (last finisher) ============
    __syncthreads();
    if (t == 0) {
        __threadfence();
        if (atomicAdd(&g_finish, 1) == GRID - 1) {
            g_arrive = 0;
            g_release = 0;
            for (int i = 0; i < H_DIM; i++) { g_sum[i] = 0.f; g_sumsq[i] = 0.f; }
            __threadfence();
            g_finish = 0;
        }
    }
}

// -------- launch --------
extern "C" void kernel_launch(void* const* d_in, const int* in_sizes, int n_in,
                              void* d_out, int out_size) {
    (void)in_sizes; (void)n_in; (void)out_size;
    const float* edge_attr = (const float*)d_in[0];
    const float* nf        = (const float*)d_in[1];
    const int*   eidx      = (const int*)d_in[2];
    // d_in[3..8] = edge-encoder weights: dead code in the reference
    const float* W1    = (const float*)d_in[9];
    const float* b1    = (const float*)d_in[10];
    const float* gamma = (const float*)d_in[11];
    const float* beta  = (const float*)d_in[12];
    const float* W2    = (const float*)d_in[13];
    const float* b2    = (const float*)d_in[14];
    const float* Wv    = (const float*)d_in[15];
    const float* bv    = (const float*)d_in[16];
    const float* Wo    = (const float*)d_in[17];
    const float* bo    = (const float*)d_in[18];
    const float* Wp    = (const float*)d_in[19];
    const float* bp    = (const float*)d_in[20];
    float* out = (float*)d_out;

    fused<<<GRID, 256>>>(edge_attr, nf, eidx, W1, b1, gamma, beta,
                         W2, b2, Wv, bv, Wo, bo, Wp, bp, out);
}

// round 7
// speedup vs baseline: 1.4242x; 1.4242x over previous
#include <cuda_runtime.h>
#include <cstdint>

#define E_NUM   500000
#define H_DIM   256
#define PAIRS   (E_NUM / 2)      // 250000
#define BN_EPS  1e-5f
#define GRID    296              // 148 SMs x 2 co-resident blocks
#define PER1    848              // pairs/block for stats, blocks 1..295
#define NTILES  31250            // E/16 edge tiles for tensor phase 2
#define NWARPS  (GRID * 8)       // 2368 warps

typedef unsigned long long u64;

// -------- device scratch (static, no allocation) --------
__device__ float g_sum[H_DIM];                     // zero-init
__device__ float g_sumsq[H_DIM];
__device__ __align__(16) float g_ncf[(size_t)E_NUM * 8];  // plain nc [E,8], 16MB
__device__ float g_Craw[H_DIM * 8];                // W2@Wv@Wo@Wp
__device__ float g_biaspart[8];                    // b2@P2 + bv@P1 + bo@Wp + bp
__device__ unsigned g_arrive = 0;
__device__ volatile unsigned g_release = 0;
__device__ unsigned g_finish = 0;

// -------- f32x2 helpers (phase 1) --------
__device__ __forceinline__ u64 pack2(float lo, float hi) {
    u64 r;
    asm("mov.b64 %0, {%1, %2};" : "=l"(r)
        : "r"(__float_as_uint(lo)), "r"(__float_as_uint(hi)));
    return r;
}
__device__ __forceinline__ void unpack2(u64 v, float &lo, float &hi) {
    unsigned int a, b;
    asm("mov.b64 {%0, %1}, %2;" : "=r"(a), "=r"(b) : "l"(v));
    lo = __uint_as_float(a); hi = __uint_as_float(b);
}
__device__ __forceinline__ u64 fma2(u64 a, u64 b, u64 c) {
    u64 d;
    asm("fma.rn.f32x2 %0, %1, %2, %3;" : "=l"(d) : "l"(a), "l"(b), "l"(c));
    return d;
}
__device__ __forceinline__ u64 add2(u64 a, u64 b) {
    u64 d;
    asm("add.rn.f32x2 %0, %1, %2;" : "=l"(d) : "l"(a), "l"(b));
    return d;
}
__device__ __forceinline__ u64 relu2(u64 h) {
    float lo, hi; unpack2(h, lo, hi);
    return pack2(fmaxf(lo, 0.f), fmaxf(hi, 0.f));
}
__device__ __forceinline__ float wred(float v) {
    v += __shfl_down_sync(0xffffffffu, v, 16);
    v += __shfl_down_sync(0xffffffffu, v, 8);
    v += __shfl_down_sync(0xffffffffu, v, 4);
    v += __shfl_down_sync(0xffffffffu, v, 2);
    v += __shfl_down_sync(0xffffffffu, v, 1);
    return v;
}

// -------- tf32 mma helpers (phase 2) --------
__device__ __forceinline__ unsigned tf32r(float x) {
    unsigned u;
    asm("cvt.rna.tf32.f32 %0, %1;" : "=r"(u) : "f"(x));
    return u;
}
// d = A@B + cin  (fresh d regs; cin passed separately)
__device__ __forceinline__ void mma_init(float &d0, float &d1, float &d2, float &d3,
    unsigned a0, unsigned a1, unsigned a2, unsigned a3,
    unsigned b0, unsigned b1,
    float c0, float c1, float c2, float c3) {
    asm("mma.sync.aligned.m16n8k8.row.col.f32.tf32.tf32.f32 "
        "{%0,%1,%2,%3}, {%4,%5,%6,%7}, {%8,%9}, {%10,%11,%12,%13};"
        : "=f"(d0), "=f"(d1), "=f"(d2), "=f"(d3)
        : "r"(a0), "r"(a1), "r"(a2), "r"(a3), "r"(b0), "r"(b1),
          "f"(c0), "f"(c1), "f"(c2), "f"(c3));
}
// c += A@B (accumulate in place)
__device__ __forceinline__ void mma_acc(float &c0, float &c1, float &c2, float &c3,
    unsigned a0, unsigned a1, unsigned a2, unsigned a3,
    unsigned b0, unsigned b1) {
    asm("mma.sync.aligned.m16n8k8.row.col.f32.tf32.tf32.f32 "
        "{%0,%1,%2,%3}, {%4,%5,%6,%7}, {%8,%9}, {%0,%1,%2,%3};"
        : "+f"(c0), "+f"(c1), "+f"(c2), "+f"(c3)
        : "r"(a0), "r"(a1), "r"(a2), "r"(a3), "r"(b0), "r"(b1));
}

__global__ void __launch_bounds__(256, 2)
fused(const float* __restrict__ ea, const float* __restrict__ nf,
      const int*   __restrict__ eidx,
      const float* __restrict__ W1, const float* __restrict__ b1,
      const float* __restrict__ gamma, const float* __restrict__ beta,
      const float* __restrict__ W2, const float* __restrict__ b2,
      const float* __restrict__ Wv, const float* __restrict__ bv,
      const float* __restrict__ Wo, const float* __restrict__ bo,
      const float* __restrict__ Wp, const float* __restrict__ bp,
      float* __restrict__ out)
{
    // union: phase1 ncs (u64[2048]=16KB) / block0 chain bufs (2x2304 floats)
    //        / phase2 frag tables: w1f 8KB | mf 8KB | b1f 1KB
    __shared__ __align__(16) unsigned char s_buf[18432];
    __shared__ __align__(16) u64 w1s[H_DIM * 8];   // W1^T duplicated (phase 1)
    __shared__ u64 b1s[H_DIM];
    __shared__ float dhf[8];
    __shared__ float a_s[H_DIM], c_s[H_DIM];

    const int t = threadIdx.x;
    const int b = blockIdx.x;
    const int lane = t & 31, warp = t >> 5;

    // duplicated W1^T / b1 tables for phase 1
    #pragma unroll
    for (int d = 0; d < 8; d++) {
        float v = W1[d * H_DIM + t];
        w1s[t * 8 + d] = pack2(v, v);
    }
    { float bb = b1[t]; b1s[t] = pack2(bb, bb); }

    if (b == 0) {
        // ============ weight chain (overlaps the stats pass) ============
        float* bufA = (float*)s_buf;      // 256 rows x 9 floats (padded)
        float* bufB = bufA + 2304;
        for (int i = t; i < H_DIM * 8; i += 256)
            bufA[(i >> 3) * 9 + (i & 7)] = Wp[i];
        __syncthreads();
        float biask = 0.f;
        for (int j = lane; j < H_DIM; j += 32) biask += bo[j] * bufA[j * 9 + warp];
        // P1 = Wo @ Wp
        for (int jj = warp; jj < H_DIM; jj += 8) {
            float a0=0,a1=0,a2=0,a3=0,a4=0,a5=0,a6=0,a7=0;
            #pragma unroll
            for (int qb = 0; qb < 8; qb++) {
                int q = qb * 32 + lane;
                float av = Wo[jj * H_DIM + q];
                const float* ir = bufA + q * 9;
                a0 += av*ir[0]; a1 += av*ir[1]; a2 += av*ir[2]; a3 += av*ir[3];
                a4 += av*ir[4]; a5 += av*ir[5]; a6 += av*ir[6]; a7 += av*ir[7];
            }
            a0=wred(a0); a1=wred(a1); a2=wred(a2); a3=wred(a3);
            a4=wred(a4); a5=wred(a5); a6=wred(a6); a7=wred(a7);
            if (lane == 0) {
                float* orow = bufB + jj * 9;
                orow[0]=a0; orow[1]=a1; orow[2]=a2; orow[3]=a3;
                orow[4]=a4; orow[5]=a5; orow[6]=a6; orow[7]=a7;
            }
        }
        __syncthreads();
        for (int j = lane; j < H_DIM; j += 32) biask += bv[j] * bufB[j * 9 + warp];
        // P2 = Wv @ P1
        for (int jj = warp; jj < H_DIM; jj += 8) {
            float a0=0,a1=0,a2=0,a3=0,a4=0,a5=0,a6=0,a7=0;
            #pragma unroll
            for (int qb = 0; qb < 8; qb++) {
                int q = qb * 32 + lane;
                float av = Wv[jj * H_DIM + q];
                const float* ir = bufB + q * 9;
                a0 += av*ir[0]; a1 += av*ir[1]; a2 += av*ir[2]; a3 += av*ir[3];
                a4 += av*ir[4]; a5 += av*ir[5]; a6 += av*ir[6]; a7 += av*ir[7];
            }
            a0=wred(a0); a1=wred(a1); a2=wred(a2); a3=wred(a3);
            a4=wred(a4); a5=wred(a5); a6=wred(a6); a7=wred(a7);
            if (lane == 0) {
                float* orow = bufA + jj * 9;
                orow[0]=a0; orow[1]=a1; orow[2]=a2; orow[3]=a3;
                orow[4]=a4; orow[5]=a5; orow[6]=a6; orow[7]=a7;
            }
        }
        __syncthreads();
        for (int j = lane; j < H_DIM; j += 32) biask += b2[j] * bufA[j * 9 + warp];
        // Craw = W2 @ P2 -> global
        for (int jj = warp; jj < H_DIM; jj += 8) {
            float a0=0,a1=0,a2=0,a3=0,a4=0,a5=0,a6=0,a7=0;
            #pragma unroll
            for (int qb = 0; qb < 8; qb++) {
                int q = qb * 32 + lane;
                float av = W2[jj * H_DIM + q];
                const float* ir = bufA + q * 9;
                a0 += av*ir[0]; a1 += av*ir[1]; a2 += av*ir[2]; a3 += av*ir[3];
                a4 += av*ir[4]; a5 += av*ir[5]; a6 += av*ir[6]; a7 += av*ir[7];
            }
            a0=wred(a0); a1=wred(a1); a2=wred(a2); a3=wred(a3);
            a4=wred(a4); a5=wred(a5); a6=wred(a6); a7=wred(a7);
            if (lane == 0) {
                float* orow = g_Craw + jj * 8;
                orow[0]=a0; orow[1]=a1; orow[2]=a2; orow[3]=a3;
                orow[4]=a4; orow[5]=a5; orow[6]=a6; orow[7]=a7;
            }
        }
        biask = wred(biask);
        if (lane == 0) g_biaspart[warp] = biask + bp[warp];
    } else {
        // ============ phase 1: gather + cache nc + relu stats ============
        int s1 = (b - 1) * PER1;
        int e1 = s1 + PER1; if (e1 > PAIRS) e1 = PAIRS;
        u64* ncs = (u64*)s_buf;
        const float4* nf4 = (const float4*)nf;

        const ulonglong2* wd = (const ulonglong2*)&w1s[t * 8];
        ulonglong2 w01 = wd[0], w23 = wd[1], w45 = wd[2], w67 = wd[3];
        u64 bdup = b1s[t];
        u64 sum2 = 0ull, sq2 = 0ull;

        for (int base = s1; base < e1; base += 256) {
            int cnt = e1 - base; if (cnt > 256) cnt = 256;
            __syncthreads();
            if (t < cnt) {
                int p  = base + t;
                int e0 = 2 * p;
                int sA = eidx[e0],         sB = eidx[e0 + 1];
                int dA = eidx[E_NUM + e0], dB = eidx[E_NUM + e0 + 1];
                float4 sa0 = nf4[2*sA], sa1 = nf4[2*sA+1];
                float4 da0 = nf4[2*dA], da1 = nf4[2*dA+1];
                float4 sb0 = nf4[2*sB], sb1 = nf4[2*sB+1];
                float4 db0 = nf4[2*dB], db1 = nf4[2*dB+1];
                // lo = edge 2p, hi = edge 2p+1
                float l0 = 0.5f*(sa0.x+da0.x), h0 = 0.5f*(sb0.x+db0.x);
                float l1 = 0.5f*(sa0.y+da0.y), h1 = 0.5f*(sb0.y+db0.y);
                float l2 = 0.5f*(sa0.z+da0.z), h2 = 0.5f*(sb0.z+db0.z);
                float l3 = 0.5f*(sa0.w+da0.w), h3 = 0.5f*(sb0.w+db0.w);
                float l4 = 0.5f*(sa1.x+da1.x), h4 = 0.5f*(sb1.x+db1.x);
                float l5 = 0.5f*(sa1.y+da1.y), h5 = 0.5f*(sb1.y+db1.y);
                float l6 = 0.5f*(sa1.z+da1.z), h6 = 0.5f*(sb1.z+db1.z);
                float l7 = 0.5f*(sa1.w+da1.w), h7 = 0.5f*(sb1.w+db1.w);
                u64 ncp[8];
                ncp[0] = pack2(l0, h0); ncp[1] = pack2(l1, h1);
                ncp[2] = pack2(l2, h2); ncp[3] = pack2(l3, h3);
                ncp[4] = pack2(l4, h4); ncp[5] = pack2(l5, h5);
                ncp[6] = pack2(l6, h6); ncp[7] = pack2(l7, h7);
                #pragma unroll
                for (int d = 0; d < 8; d++) ncs[t * 8 + d] = ncp[d];
                // plain [E,8] rows for tensor phase 2
                float4* nr = (float4*)(g_ncf + (size_t)(2 * p) * 8);
                nr[0] = make_float4(l0, l1, l2, l3);
                nr[1] = make_float4(l4, l5, l6, l7);
                nr[2] = make_float4(h0, h1, h2, h3);
                nr[3] = make_float4(h4, h5, h6, h7);
            }
            __syncthreads();
            for (int e2 = 0; e2 < cnt; e2++) {
                const ulonglong2* c = (const ulonglong2*)&ncs[e2 * 8];
                ulonglong2 c01 = c[0], c23 = c[1], c45 = c[2], c67 = c[3];
                u64 h = bdup;
                h = fma2(c01.x, w01.x, h); h = fma2(c01.y, w01.y, h);
                h = fma2(c23.x, w23.x, h); h = fma2(c23.y, w23.y, h);
                h = fma2(c45.x, w45.x, h); h = fma2(c45.y, w45.y, h);
                h = fma2(c67.x, w67.x, h); h = fma2(c67.y, w67.y, h);
                h = relu2(h);
                sum2 = add2(sum2, h);
                sq2  = fma2(h, h, sq2);
            }
        }
        float slo, shi, qlo, qhi;
        unpack2(sum2, slo, shi);
        unpack2(sq2, qlo, qhi);
        atomicAdd(&g_sum[t],   slo + shi);
        atomicAdd(&g_sumsq[t], qlo + qhi);
    }

    // ============ grid barrier ============
    __syncthreads();
    if (t == 0) {
        __threadfence();
        if (atomicAdd(&g_arrive, 1) == GRID - 1) {
            g_release = 1;
        } else {
            while (g_release == 0) { }
        }
        __threadfence();
    }
    __syncthreads();

    // ============ finalize BN, dh, fragment tables (per block) ============
    {
        const float invE = 1.f / (float)E_NUM;
        float mu  = g_sum[t] * invE;
        float var = g_sumsq[t] * invE - mu * mu;
        float aj  = gamma[t] * rsqrtf(var + BN_EPS);
        a_s[t] = aj;
        c_s[t] = beta[t] - mu * aj;
    }
    __syncthreads();
    {   // dh[k] = 0.5*(c@Craw[:,k] + biaspart[k]); warp w owns k=w
        float acc = 0.f;
        for (int j = lane; j < H_DIM; j += 32) acc += c_s[j] * g_Craw[j * 8 + warp];
        acc = wred(acc);
        if (lane == 0) dhf[warp] = 0.5f * (acc + g_biaspart[warp]);
    }
    // fragment tables (tf32-preconverted), conflict-free by lane
    float2* w1f = (float2*)s_buf;                    // [1024] GEMM1 B frags
    float2* mf  = (float2*)(s_buf + 8192);           // [1024] GEMM2 B frags
    float2* b1f = (float2*)(s_buf + 16384);          // [128]  b1 col pairs
    for (int i = t; i < 1024; i += 256) {
        int q = i >> 5, l = i & 31;
        int kk = l & 3, nn = l >> 2;
        // W1 chunk B-frag: b0 = W1[kk, q*8+nn], b1 = W1[kk+4, q*8+nn]
        float w0 = W1[kk * H_DIM + q * 8 + nn];
        float w1v = W1[(kk + 4) * H_DIM + q * 8 + nn];
        w1f[i] = make_float2(__uint_as_float(tf32r(w0)), __uint_as_float(tf32r(w1v)));
        // M chunk B-frag: M[j,o] = 0.5*a[j]*Craw[j,o]
        int j0 = q * 8 + kk;
        float m0 = 0.5f * a_s[j0] * g_Craw[j0 * 8 + nn];
        float m1 = 0.5f * a_s[j0 + 4] * g_Craw[(j0 + 4) * 8 + nn];
        mf[i] = make_float2(__uint_as_float(tf32r(m0)), __uint_as_float(tf32r(m1)));
    }
    for (int i = t; i < 128; i += 256) {
        int q = i >> 2, q4 = i & 3;
        b1f[i] = make_float2(b1[q * 8 + 2 * q4], b1[q * 8 + 2 * q4 + 1]);
    }
    __syncthreads();

    // ============ phase 2: tensor-core contraction, 16 edges/tile ============
    {
        const int warp_gid = b * 8 + warp;
        const int g = lane >> 2, q4 = lane & 3;
        const int src0 = (g << 2) | (q4 >> 1), src2 = src0 + 2;
        const bool odd = lane & 1;
        const float dh0 = dhf[2 * q4], dh1 = dhf[2 * q4 + 1];

        for (int tau = warp_gid; tau < NTILES; tau += NWARPS) {
            int pe = tau << 4;
            const float* r0 = g_ncf + (size_t)(pe + g) * 8;
            const float* r8 = r0 + 64;
            unsigned a0 = tf32r(r0[q4]);
            unsigned a1 = tf32r(r8[q4]);
            unsigned a2 = tf32r(r0[q4 + 4]);
            unsigned a3 = tf32r(r8[q4 + 4]);
            float c0 = dh0, c1 = dh1, c2 = dh0, c3 = dh1;

            #pragma unroll 4
            for (int q = 0; q < 32; q++) {
                float2 bp = b1f[(q << 2) | q4];
                float2 wv = w1f[(q << 5) | lane];
                float h0, h1, h2, h3;
                mma_init(h0, h1, h2, h3, a0, a1, a2, a3,
                         __float_as_uint(wv.x), __float_as_uint(wv.y),
                         bp.x, bp.y, bp.x, bp.y);
                unsigned hr0 = tf32r(fmaxf(h0, 0.f));
                unsigned hr1 = tf32r(fmaxf(h1, 0.f));
                unsigned hr2 = tf32r(fmaxf(h2, 0.f));
                unsigned hr3 = tf32r(fmaxf(h3, 0.f));
                unsigned s00 = __shfl_sync(0xffffffffu, hr0, src0);
                unsigned s01 = __shfl_sync(0xffffffffu, hr1, src0);
                unsigned s02 = __shfl_sync(0xffffffffu, hr2, src0);
                unsigned s03 = __shfl_sync(0xffffffffu, hr3, src0);
                unsigned s20 = __shfl_sync(0xffffffffu, hr0, src2);
                unsigned s21 = __shfl_sync(0xffffffffu, hr1, src2);
                unsigned s22 = __shfl_sync(0xffffffffu, hr2, src2);
                unsigned s23 = __shfl_sync(0xffffffffu, hr3, src2);
                unsigned x0 = odd ? s01 : s00;   // h(g,   q4)
                unsigned x1 = odd ? s03 : s02;   // h(g+8, q4)
                unsigned x2 = odd ? s21 : s20;   // h(g,   q4+4)
                unsigned x3 = odd ? s23 : s22;   // h(g+8, q4+4)
                float2 mv = mf[(q << 5) | lane];
                mma_acc(c0, c1, c2, c3, x0, x1, x2, x3,
                        __float_as_uint(mv.x), __float_as_uint(mv.y));
            }

            // epilogue: rows pe+g, pe+g+8; cols 2q4, 2q4+1 (contiguous pairs)
            size_t o1 = (size_t)(pe + g) * 8 + 2 * q4;
            size_t o2 = o1 + 64;
            float2 e1 = *(const float2*)(ea + o1);
            float2 e2v = *(const float2*)(ea + o2);
            *(float2*)(out + o1) = make_float2(e1.x + c0, e1.y + c1);
            *(float2*)(out + o2) = make_float2(e2v.x + c2, e2v.y + c3);
        }
    }

    // ============ reset (last finisher) ============
    __syncthreads();
    if (t == 0) {
        __threadfence();
        if (atomicAdd(&g_finish, 1) == GRID - 1) {
            g_arrive = 0;
            g_release = 0;
            for (int i = 0; i < H_DIM; i++) { g_sum[i] = 0.f; g_sumsq[i] = 0.f; }
            __threadfence();
            g_finish = 0;
        }
    }
}

// -------- launch --------
extern "C" void kernel_launch(void* const* d_in, const int* in_sizes, int n_in,
                              void* d_out, int out_size) {
    (void)in_sizes; (void)n_in; (void)out_size;
    const float* edge_attr = (const float*)d_in[0];
    const float* nf        = (const float*)d_in[1];
    const int*   eidx      = (const int*)d_in[2];
    // d_in[3..8] = edge-encoder weights: dead code in the reference
    const float* W1    = (const float*)d_in[9];
    const float* b1    = (const float*)d_in[10];
    const float* gamma = (const float*)d_in[11];
    const float* beta  = (const float*)d_in[12];
    const float* W2    = (const float*)d_in[13];
    const float* b2    = (const float*)d_in[14];
    const float* Wv    = (const float*)d_in[15];
    const float* bv    = (const float*)d_in[16];
    const float* Wo    = (const float*)d_in[17];
    const float* bo    = (const float*)d_in[18];
    const float* Wp    = (const float*)d_in[19];
    const float* bp    = (const float*)d_in[20];
    float* out = (float*)d_out;

    fused<<<GRID, 256>>>(edge_attr, nf, eidx, W1, b1, gamma, beta,
                         W2, b2, Wv, bv, Wo, bo, Wp, bp, out);
}

// round 8
// speedup vs baseline: 1.6770x; 1.1775x over previous
#include <cuda_runtime.h>
#include <cstdint>

#define E_NUM   500000
#define H_DIM   256
#define PAIRS   (E_NUM / 2)      // 250000
#define BN_EPS  1e-5f
#define GRID    296              // 148 SMs x 2 co-resident blocks
#define PER1    848              // pairs/block for stats, blocks 1..295
#define NTILES  31250            // E/16 edge tiles for tensor phase 2
#define NWARPS  (GRID * 8)       // 2368 warps

typedef unsigned long long u64;

// -------- device scratch (static, no allocation) --------
__device__ float g_sum[H_DIM];                     // zero-init
__device__ float g_sumsq[H_DIM];
__device__ __align__(16) float g_ncf[(size_t)E_NUM * 8];  // plain nc [E,8], 16MB
__device__ float g_Craw[H_DIM * 8];                // W2@Wv@Wo@Wp
__device__ float g_biaspart[8];                    // b2@P2 + bv@P1 + bo@Wp + bp
__device__ unsigned g_arrive = 0;
__device__ volatile unsigned g_release = 0;
__device__ unsigned g_finish = 0;

// -------- f32x2 helpers (phase 1) --------
__device__ __forceinline__ u64 pack2(float lo, float hi) {
    u64 r;
    asm("mov.b64 %0, {%1, %2};" : "=l"(r)
        : "r"(__float_as_uint(lo)), "r"(__float_as_uint(hi)));
    return r;
}
__device__ __forceinline__ void unpack2(u64 v, float &lo, float &hi) {
    unsigned int a, b;
    asm("mov.b64 {%0, %1}, %2;" : "=r"(a), "=r"(b) : "l"(v));
    lo = __uint_as_float(a); hi = __uint_as_float(b);
}
__device__ __forceinline__ u64 fma2(u64 a, u64 b, u64 c) {
    u64 d;
    asm("fma.rn.f32x2 %0, %1, %2, %3;" : "=l"(d) : "l"(a), "l"(b), "l"(c));
    return d;
}
__device__ __forceinline__ u64 add2(u64 a, u64 b) {
    u64 d;
    asm("add.rn.f32x2 %0, %1, %2;" : "=l"(d) : "l"(a), "l"(b));
    return d;
}
__device__ __forceinline__ u64 relu2(u64 h) {
    float lo, hi; unpack2(h, lo, hi);
    return pack2(fmaxf(lo, 0.f), fmaxf(hi, 0.f));
}
__device__ __forceinline__ float wred(float v) {
    v += __shfl_down_sync(0xffffffffu, v, 16);
    v += __shfl_down_sync(0xffffffffu, v, 8);
    v += __shfl_down_sync(0xffffffffu, v, 4);
    v += __shfl_down_sync(0xffffffffu, v, 2);
    v += __shfl_down_sync(0xffffffffu, v, 1);
    return v;
}

// -------- tf32 mma helpers (phase 2) --------
__device__ __forceinline__ unsigned tf32r(float x) {
    unsigned u;
    asm("cvt.rna.tf32.f32 %0, %1;" : "=r"(u) : "f"(x));
    return u;
}
__device__ __forceinline__ void mma_init(float &d0, float &d1, float &d2, float &d3,
    unsigned a0, unsigned a1, unsigned a2, unsigned a3,
    unsigned b0, unsigned b1,
    float c0, float c1, float c2, float c3) {
    asm("mma.sync.aligned.m16n8k8.row.col.f32.tf32.tf32.f32 "
        "{%0,%1,%2,%3}, {%4,%5,%6,%7}, {%8,%9}, {%10,%11,%12,%13};"
        : "=f"(d0), "=f"(d1), "=f"(d2), "=f"(d3)
        : "r"(a0), "r"(a1), "r"(a2), "r"(a3), "r"(b0), "r"(b1),
          "f"(c0), "f"(c1), "f"(c2), "f"(c3));
}
__device__ __forceinline__ void mma_acc(float &c0, float &c1, float &c2, float &c3,
    unsigned a0, unsigned a1, unsigned a2, unsigned a3,
    unsigned b0, unsigned b1) {
    asm("mma.sync.aligned.m16n8k8.row.col.f32.tf32.tf32.f32 "
        "{%0,%1,%2,%3}, {%4,%5,%6,%7}, {%8,%9}, {%0,%1,%2,%3};"
        : "+f"(c0), "+f"(c1), "+f"(c2), "+f"(c3)
        : "r"(a0), "r"(a1), "r"(a2), "r"(a3), "r"(b0), "r"(b1));
}

__global__ void __launch_bounds__(256, 2)
fused(const float* __restrict__ ea, const float* __restrict__ nf,
      const int*   __restrict__ eidx,
      const float* __restrict__ W1, const float* __restrict__ b1,
      const float* __restrict__ gamma, const float* __restrict__ beta,
      const float* __restrict__ W2, const float* __restrict__ b2,
      const float* __restrict__ Wv, const float* __restrict__ bv,
      const float* __restrict__ Wo, const float* __restrict__ bo,
      const float* __restrict__ Wp, const float* __restrict__ bp,
      float* __restrict__ out)
{
    __shared__ __align__(16) unsigned char s_buf[18432];
    __shared__ __align__(16) u64 w1s[H_DIM * 8];   // W1^T duplicated (phase 1)
    __shared__ u64 b1s[H_DIM];
    __shared__ float dhf[8];
    __shared__ float a_s[H_DIM], c_s[H_DIM];

    const int t = threadIdx.x;
    const int b = blockIdx.x;
    const int lane = t & 31, warp = t >> 5;

    #pragma unroll
    for (int d = 0; d < 8; d++) {
        float v = W1[d * H_DIM + t];
        w1s[t * 8 + d] = pack2(v, v);
    }
    { float bb = b1[t]; b1s[t] = pack2(bb, bb); }

    if (b == 0) {
        // ============ weight chain (overlaps the stats pass) ============
        float* bufA = (float*)s_buf;
        float* bufB = bufA + 2304;
        for (int i = t; i < H_DIM * 8; i += 256)
            bufA[(i >> 3) * 9 + (i & 7)] = Wp[i];
        __syncthreads();
        float biask = 0.f;
        for (int j = lane; j < H_DIM; j += 32) biask += bo[j] * bufA[j * 9 + warp];
        for (int jj = warp; jj < H_DIM; jj += 8) {
            float a0=0,a1=0,a2=0,a3=0,a4=0,a5=0,a6=0,a7=0;
            #pragma unroll
            for (int qb = 0; qb < 8; qb++) {
                int q = qb * 32 + lane;
                float av = Wo[jj * H_DIM + q];
                const float* ir = bufA + q * 9;
                a0 += av*ir[0]; a1 += av*ir[1]; a2 += av*ir[2]; a3 += av*ir[3];
                a4 += av*ir[4]; a5 += av*ir[5]; a6 += av*ir[6]; a7 += av*ir[7];
            }
            a0=wred(a0); a1=wred(a1); a2=wred(a2); a3=wred(a3);
            a4=wred(a4); a5=wred(a5); a6=wred(a6); a7=wred(a7);
            if (lane == 0) {
                float* orow = bufB + jj * 9;
                orow[0]=a0; orow[1]=a1; orow[2]=a2; orow[3]=a3;
                orow[4]=a4; orow[5]=a5; orow[6]=a6; orow[7]=a7;
            }
        }
        __syncthreads();
        for (int j = lane; j < H_DIM; j += 32) biask += bv[j] * bufB[j * 9 + warp];
        for (int jj = warp; jj < H_DIM; jj += 8) {
            float a0=0,a1=0,a2=0,a3=0,a4=0,a5=0,a6=0,a7=0;
            #pragma unroll
            for (int qb = 0; qb < 8; qb++) {
                int q = qb * 32 + lane;
                float av = Wv[jj * H_DIM + q];
                const float* ir = bufB + q * 9;
                a0 += av*ir[0]; a1 += av*ir[1]; a2 += av*ir[2]; a3 += av*ir[3];
                a4 += av*ir[4]; a5 += av*ir[5]; a6 += av*ir[6]; a7 += av*ir[7];
            }
            a0=wred(a0); a1=wred(a1); a2=wred(a2); a3=wred(a3);
            a4=wred(a4); a5=wred(a5); a6=wred(a6); a7=wred(a7);
            if (lane == 0) {
                float* orow = bufA + jj * 9;
                orow[0]=a0; orow[1]=a1; orow[2]=a2; orow[3]=a3;
                orow[4]=a4; orow[5]=a5; orow[6]=a6; orow[7]=a7;
            }
        }
        __syncthreads();
        for (int j = lane; j < H_DIM; j += 32) biask += b2[j] * bufA[j * 9 + warp];
        for (int jj = warp; jj < H_DIM; jj += 8) {
            float a0=0,a1=0,a2=0,a3=0,a4=0,a5=0,a6=0,a7=0;
            #pragma unroll
            for (int qb = 0; qb < 8; qb++) {
                int q = qb * 32 + lane;
                float av = W2[jj * H_DIM + q];
                const float* ir = bufA + q * 9;
                a0 += av*ir[0]; a1 += av*ir[1]; a2 += av*ir[2]; a3 += av*ir[3];
                a4 += av*ir[4]; a5 += av*ir[5]; a6 += av*ir[6]; a7 += av*ir[7];
            }
            a0=wred(a0); a1=wred(a1); a2=wred(a2); a3=wred(a3);
            a4=wred(a4); a5=wred(a5); a6=wred(a6); a7=wred(a7);
            if (lane == 0) {
                float* orow = g_Craw + jj * 8;
                orow[0]=a0; orow[1]=a1; orow[2]=a2; orow[3]=a3;
                orow[4]=a4; orow[5]=a5; orow[6]=a6; orow[7]=a7;
            }
        }
        biask = wred(biask);
        if (lane == 0) g_biaspart[warp] = biask + bp[warp];
    } else {
        // ============ phase 1: gather + cache nc + relu stats ============
        int s1 = (b - 1) * PER1;
        int e1 = s1 + PER1; if (e1 > PAIRS) e1 = PAIRS;
        u64* ncs = (u64*)s_buf;
        const float4* nf4 = (const float4*)nf;

        const ulonglong2* wd = (const ulonglong2*)&w1s[t * 8];
        ulonglong2 w01 = wd[0], w23 = wd[1], w45 = wd[2], w67 = wd[3];
        u64 bdup = b1s[t];
        u64 sum2 = 0ull, sq2 = 0ull;

        for (int base = s1; base < e1; base += 256) {
            int cnt = e1 - base; if (cnt > 256) cnt = 256;
            __syncthreads();
            if (t < cnt) {
                int p  = base + t;
                int e0 = 2 * p;
                int sA = eidx[e0],         sB = eidx[e0 + 1];
                int dA = eidx[E_NUM + e0], dB = eidx[E_NUM + e0 + 1];
                float4 sa0 = nf4[2*sA], sa1 = nf4[2*sA+1];
                float4 da0 = nf4[2*dA], da1 = nf4[2*dA+1];
                float4 sb0 = nf4[2*sB], sb1 = nf4[2*sB+1];
                float4 db0 = nf4[2*dB], db1 = nf4[2*dB+1];
                float l0 = 0.5f*(sa0.x+da0.x), h0 = 0.5f*(sb0.x+db0.x);
                float l1 = 0.5f*(sa0.y+da0.y), h1 = 0.5f*(sb0.y+db0.y);
                float l2 = 0.5f*(sa0.z+da0.z), h2 = 0.5f*(sb0.z+db0.z);
                float l3 = 0.5f*(sa0.w+da0.w), h3 = 0.5f*(sb0.w+db0.w);
                float l4 = 0.5f*(sa1.x+da1.x), h4 = 0.5f*(sb1.x+db1.x);
                float l5 = 0.5f*(sa1.y+da1.y), h5 = 0.5f*(sb1.y+db1.y);
                float l6 = 0.5f*(sa1.z+da1.z), h6 = 0.5f*(sb1.z+db1.z);
                float l7 = 0.5f*(sa1.w+da1.w), h7 = 0.5f*(sb1.w+db1.w);
                u64 ncp[8];
                ncp[0] = pack2(l0, h0); ncp[1] = pack2(l1, h1);
                ncp[2] = pack2(l2, h2); ncp[3] = pack2(l3, h3);
                ncp[4] = pack2(l4, h4); ncp[5] = pack2(l5, h5);
                ncp[6] = pack2(l6, h6); ncp[7] = pack2(l7, h7);
                #pragma unroll
                for (int d = 0; d < 8; d++) ncs[t * 8 + d] = ncp[d];
                float4* nr = (float4*)(g_ncf + (size_t)(2 * p) * 8);
                nr[0] = make_float4(l0, l1, l2, l3);
                nr[1] = make_float4(l4, l5, l6, l7);
                nr[2] = make_float4(h0, h1, h2, h3);
                nr[3] = make_float4(h4, h5, h6, h7);
            }
            __syncthreads();
            for (int e2 = 0; e2 < cnt; e2++) {
                const ulonglong2* c = (const ulonglong2*)&ncs[e2 * 8];
                ulonglong2 c01 = c[0], c23 = c[1], c45 = c[2], c67 = c[3];
                u64 h = bdup;
                h = fma2(c01.x, w01.x, h); h = fma2(c01.y, w01.y, h);
                h = fma2(c23.x, w23.x, h); h = fma2(c23.y, w23.y, h);
                h = fma2(c45.x, w45.x, h); h = fma2(c45.y, w45.y, h);
                h = fma2(c67.x, w67.x, h); h = fma2(c67.y, w67.y, h);
                h = relu2(h);
                sum2 = add2(sum2, h);
                sq2  = fma2(h, h, sq2);
            }
        }
        float slo, shi, qlo, qhi;
        unpack2(sum2, slo, shi);
        unpack2(sq2, qlo, qhi);
        atomicAdd(&g_sum[t],   slo + shi);
        atomicAdd(&g_sumsq[t], qlo + qhi);
    }

    // ============ grid barrier ============
    __syncthreads();
    if (t == 0) {
        __threadfence();
        if (atomicAdd(&g_arrive, 1) == GRID - 1) {
            g_release = 1;
        } else {
            while (g_release == 0) { }
        }
        __threadfence();
    }
    __syncthreads();

    // ============ finalize BN, dh, fragment tables (per block) ============
    {
        const float invE = 1.f / (float)E_NUM;
        float mu  = g_sum[t] * invE;
        float var = g_sumsq[t] * invE - mu * mu;
        float aj  = gamma[t] * rsqrtf(var + BN_EPS);
        a_s[t] = aj;
        c_s[t] = beta[t] - mu * aj;
    }
    __syncthreads();
    {
        float acc = 0.f;
        for (int j = lane; j < H_DIM; j += 32) acc += c_s[j] * g_Craw[j * 8 + warp];
        acc = wred(acc);
        if (lane == 0) dhf[warp] = 0.5f * (acc + g_biaspart[warp]);
    }
    // fragment tables (tf32-preconverted)
    float2* w1f = (float2*)s_buf;                    // [1024] GEMM1 B frags
    float2* mf  = (float2*)(s_buf + 8192);           // [1024] GEMM2 B frags (tau-permuted rows)
    float2* b1f = (float2*)(s_buf + 16384);          // [128]  b1 col pairs
    for (int i = t; i < 1024; i += 256) {
        int q = i >> 5, l = i & 31;
        int kk = l & 3, nn = l >> 2;
        float w0 = W1[kk * H_DIM + q * 8 + nn];
        float w1v = W1[(kk + 4) * H_DIM + q * 8 + nn];
        w1f[i] = make_float2(__uint_as_float(tf32r(w0)), __uint_as_float(tf32r(w1v)));
        // GEMM2 B rows permuted: K slot kk -> j = q*8 + 2*kk; slot kk+4 -> j = q*8 + 2*kk+1
        int j0 = q * 8 + 2 * kk;
        float m0 = 0.5f * a_s[j0] * g_Craw[j0 * 8 + nn];
        float m1 = 0.5f * a_s[j0 + 1] * g_Craw[(j0 + 1) * 8 + nn];
        mf[i] = make_float2(__uint_as_float(tf32r(m0)), __uint_as_float(tf32r(m1)));
    }
    for (int i = t; i < 128; i += 256) {
        int q = i >> 2, q4 = i & 3;
        b1f[i] = make_float2(b1[q * 8 + 2 * q4], b1[q * 8 + 2 * q4 + 1]);
    }
    __syncthreads();

    // ============ phase 2: tensor contraction, 2 tiles/warp interleaved ======
    {
        const int warp_gid = b * 8 + warp;
        const int g = lane >> 2, q4 = lane & 3;
        const float dh0 = dhf[2 * q4], dh1 = dhf[2 * q4 + 1];

        int tau = warp_gid;
        // paired iterations
        for (; tau + NWARPS < NTILES; tau += 2 * NWARPS) {
            int peX = tau << 4;
            int peY = (tau + NWARPS) << 4;
            const float* rX0 = g_ncf + (size_t)(peX + g) * 8;
            const float* rY0 = g_ncf + (size_t)(peY + g) * 8;
            unsigned aX0 = tf32r(rX0[q4]),      aX1 = tf32r(rX0[64 + q4]);
            unsigned aX2 = tf32r(rX0[q4 + 4]),  aX3 = tf32r(rX0[64 + q4 + 4]);
            unsigned aY0 = tf32r(rY0[q4]),      aY1 = tf32r(rY0[64 + q4]);
            unsigned aY2 = tf32r(rY0[q4 + 4]),  aY3 = tf32r(rY0[64 + q4 + 4]);
            float cX0 = dh0, cX1 = dh1, cX2 = dh0, cX3 = dh1;
            float cY0 = dh0, cY1 = dh1, cY2 = dh0, cY3 = dh1;

            #pragma unroll 4
            for (int q = 0; q < 32; q++) {
                float2 bp = b1f[(q << 2) | q4];
                float2 wv = w1f[(q << 5) | lane];
                float2 mv = mf[(q << 5) | lane];
                unsigned wb0 = __float_as_uint(wv.x), wb1 = __float_as_uint(wv.y);
                unsigned mb0 = __float_as_uint(mv.x), mb1 = __float_as_uint(mv.y);
                float hX0, hX1, hX2, hX3, hY0, hY1, hY2, hY3;
                mma_init(hX0, hX1, hX2, hX3, aX0, aX1, aX2, aX3, wb0, wb1,
                         bp.x, bp.y, bp.x, bp.y);
                mma_init(hY0, hY1, hY2, hY3, aY0, aY1, aY2, aY3, wb0, wb1,
                         bp.x, bp.y, bp.x, bp.y);
                // tau-permutation alignment: A-frag = (c0, c2, c1, c3) relu'd
                unsigned xX0 = tf32r(fmaxf(hX0, 0.f));
                unsigned xX1 = tf32r(fmaxf(hX2, 0.f));
                unsigned xX2 = tf32r(fmaxf(hX1, 0.f));
                unsigned xX3 = tf32r(fmaxf(hX3, 0.f));
                unsigned xY0 = tf32r(fmaxf(hY0, 0.f));
                unsigned xY1 = tf32r(fmaxf(hY2, 0.f));
                unsigned xY2 = tf32r(fmaxf(hY1, 0.f));
                unsigned xY3 = tf32r(fmaxf(hY3, 0.f));
                mma_acc(cX0, cX1, cX2, cX3, xX0, xX1, xX2, xX3, mb0, mb1);
                mma_acc(cY0, cY1, cY2, cY3, xY0, xY1, xY2, xY3, mb0, mb1);
            }

            size_t oX = (size_t)(peX + g) * 8 + 2 * q4;
            size_t oY = (size_t)(peY + g) * 8 + 2 * q4;
            float2 eX1 = *(const float2*)(ea + oX);
            float2 eX2 = *(const float2*)(ea + oX + 64);
            float2 eY1 = *(const float2*)(ea + oY);
            float2 eY2 = *(const float2*)(ea + oY + 64);
            *(float2*)(out + oX)      = make_float2(eX1.x + cX0, eX1.y + cX1);
            *(float2*)(out + oX + 64) = make_float2(eX2.x + cX2, eX2.y + cX3);
            *(float2*)(out + oY)      = make_float2(eY1.x + cY0, eY1.y + cY1);
            *(float2*)(out + oY + 64) = make_float2(eY2.x + cY2, eY2.y + cY3);
        }
        // leftover single tile
        if (tau < NTILES) {
            int pe = tau << 4;
            const float* r0 = g_ncf + (size_t)(pe + g) * 8;
            unsigned a0 = tf32r(r0[q4]),     a1 = tf32r(r0[64 + q4]);
            unsigned a2 = tf32r(r0[q4 + 4]), a3 = tf32r(r0[64 + q4 + 4]);
            float c0 = dh0, c1 = dh1, c2 = dh0, c3 = dh1;
            #pragma unroll 4
            for (int q = 0; q < 32; q++) {
                float2 bp = b1f[(q << 2) | q4];
                float2 wv = w1f[(q << 5) | lane];
                float2 mv = mf[(q << 5) | lane];
                float h0, h1, h2, h3;
                mma_init(h0, h1, h2, h3, a0, a1, a2, a3,
                         __float_as_uint(wv.x), __float_as_uint(wv.y),
                         bp.x, bp.y, bp.x, bp.y);
                unsigned x0 = tf32r(fmaxf(h0, 0.f));
                unsigned x1 = tf32r(fmaxf(h2, 0.f));
                unsigned x2 = tf32r(fmaxf(h1, 0.f));
                unsigned x3 = tf32r(fmaxf(h3, 0.f));
                mma_acc(c0, c1, c2, c3, x0, x1, x2, x3,
                        __float_as_uint(mv.x), __float_as_uint(mv.y));
            }
            size_t o1 = (size_t)(pe + g) * 8 + 2 * q4;
            float2 e1 = *(const float2*)(ea + o1);
            float2 e2v = *(const float2*)(ea + o1 + 64);
            *(float2*)(out + o1)      = make_float2(e1.x + c0, e1.y + c1);
            *(float2*)(out + o1 + 64) = make_float2(e2v.x + c2, e2v.y + c3);
        }
    }

    // ============ reset (last finisher) ============
    __syncthreads();
    if (t == 0) {
        __threadfence();
        if (atomicAdd(&g_finish, 1) == GRID - 1) {
            g_arrive = 0;
            g_release = 0;
            for (int i = 0; i < H_DIM; i++) { g_sum[i] = 0.f; g_sumsq[i] = 0.f; }
            __threadfence();
            g_finish = 0;
        }
    }
}

// -------- launch --------
extern "C" void kernel_launch(void* const* d_in, const int* in_sizes, int n_in,
                              void* d_out, int out_size) {
    (void)in_sizes; (void)n_in; (void)out_size;
    const float* edge_attr = (const float*)d_in[0];
    const float* nf        = (const float*)d_in[1];
    const int*   eidx      = (const int*)d_in[2];
    // d_in[3..8] = edge-encoder weights: dead code in the reference
    const float* W1    = (const float*)d_in[9];
    const float* b1    = (const float*)d_in[10];
    const float* gamma = (const float*)d_in[11];
    const float* beta  = (const float*)d_in[12];
    const float* W2    = (const float*)d_in[13];
    const float* b2    = (const float*)d_in[14];
    const float* Wv    = (const float*)d_in[15];
    const float* bv    = (const float*)d_in[16];
    const float* Wo    = (const float*)d_in[17];
    const float* bo    = (const float*)d_in[18];
    const float* Wp    = (const float*)d_in[19];
    const float* bp    = (const float*)d_in[20];
    float* out = (float*)d_out;

    fused<<<GRID, 256>>>(edge_attr, nf, eidx, W1, b1, gamma, beta,
                         W2, b2, Wv, bv, Wo, bo, Wp, bp, out);
}